// round 1
// baseline (speedup 1.0000x reference)
#include <cuda_runtime.h>
#include <cuda_bf16.h>
#include <math.h>

#define BB 64
#define LL 1024
#define HH 64
#define H2 128
#define VV 32000
#define TOK 64

// Scratch (device globals; no allocation allowed)
__device__ float g_kall[BB * LL * HH];   // 16 MB, fits in L2 for the scan
__device__ float g_r2[BB * HH];

// ---------------------------------------------------------------------------
// Kernel 1: per-token front-end: h=embed[seq]; u=relu(hW1+b1); x=uW2+b2+h;
//           LN(x); k = LN(x) @ kpW  -> g_kall
// 256 threads, 64 tokens per block, weights staged in smem.
// ---------------------------------------------------------------------------
__global__ void k1_frontend(const int* __restrict__ seq,
                            const float* __restrict__ embed,
                            const float* __restrict__ W1, const float* __restrict__ b1,
                            const float* __restrict__ W2, const float* __restrict__ b2,
                            const float* __restrict__ gamma, const float* __restrict__ beta,
                            const float* __restrict__ kpW) {
    extern __shared__ float sm[];
    float* h_sm  = sm;                    // TOK * 65 (padded)
    float* w1_sm = h_sm  + TOK * 65;      // 64*128
    float* u_sm  = w1_sm + HH * H2;       // 64*128
    float* w2_sm = u_sm  + TOK * H2;      // 128*64
    float* kp_sm = w2_sm + H2 * HH;       // 64*64
    float* b1s   = kp_sm + HH * HH;       // 128
    float* b2s   = b1s + H2;              // 64
    float* gs    = b2s + HH;              // 64
    float* bs    = gs  + HH;              // 64

    const int tid  = threadIdx.x;
    const int tok0 = blockIdx.x * TOK;

    for (int idx = tid; idx < HH * H2; idx += 256) w1_sm[idx] = W1[idx];
    for (int idx = tid; idx < H2 * HH; idx += 256) w2_sm[idx] = W2[idx];
    for (int idx = tid; idx < HH * HH; idx += 256) kp_sm[idx] = kpW[idx];
    if (tid < H2) b1s[tid] = b1[tid];
    if (tid < HH) { b2s[tid] = b2[tid]; gs[tid] = gamma[tid]; bs[tid] = beta[tid]; }

    // gather h (random embed rows; coalesced within each 256B row)
    #pragma unroll
    for (int k = 0; k < 16; k++) {
        int idx = tid + 256 * k;
        int t = idx >> 6, j = idx & 63;
        int row = seq[tok0 + t];
        h_sm[t * 65 + j] = embed[row * HH + j];
    }
    __syncthreads();

    const int tt = tid >> 4;   // 0..15
    const int ct = tid & 15;   // 0..15

    // GEMM1: u[64][128] = relu(h @ W1 + b1); 4 tok x 8 col per thread
    {
        const int r0 = tt * 4, c0 = ct * 8;
        float acc[4][8];
        #pragma unroll
        for (int r = 0; r < 4; r++)
            #pragma unroll
            for (int c = 0; c < 8; c++) acc[r][c] = 0.f;
        #pragma unroll 4
        for (int j = 0; j < HH; j++) {
            float4 wA = *(const float4*)&w1_sm[j * H2 + c0];
            float4 wB = *(const float4*)&w1_sm[j * H2 + c0 + 4];
            float hv[4];
            #pragma unroll
            for (int r = 0; r < 4; r++) hv[r] = h_sm[(r0 + r) * 65 + j];
            #pragma unroll
            for (int r = 0; r < 4; r++) {
                acc[r][0] = fmaf(hv[r], wA.x, acc[r][0]);
                acc[r][1] = fmaf(hv[r], wA.y, acc[r][1]);
                acc[r][2] = fmaf(hv[r], wA.z, acc[r][2]);
                acc[r][3] = fmaf(hv[r], wA.w, acc[r][3]);
                acc[r][4] = fmaf(hv[r], wB.x, acc[r][4]);
                acc[r][5] = fmaf(hv[r], wB.y, acc[r][5]);
                acc[r][6] = fmaf(hv[r], wB.z, acc[r][6]);
                acc[r][7] = fmaf(hv[r], wB.w, acc[r][7]);
            }
        }
        #pragma unroll
        for (int r = 0; r < 4; r++)
            #pragma unroll
            for (int c = 0; c < 8; c++)
                u_sm[(r0 + r) * H2 + c0 + c] = fmaxf(acc[r][c] + b1s[c0 + c], 0.f);
    }
    __syncthreads();

    // GEMM2 + residual: x = u @ W2 + b2 + h, in-place into h_sm. 4 tok x 4 col.
    {
        const int r0 = tt * 4, c0 = ct * 4;
        float acc[4][4];
        #pragma unroll
        for (int r = 0; r < 4; r++)
            #pragma unroll
            for (int c = 0; c < 4; c++) acc[r][c] = 0.f;
        #pragma unroll 4
        for (int j = 0; j < H2; j++) {
            float4 w = *(const float4*)&w2_sm[j * HH + c0];
            float uv[4];
            #pragma unroll
            for (int r = 0; r < 4; r++) uv[r] = u_sm[(r0 + r) * H2 + j];
            #pragma unroll
            for (int r = 0; r < 4; r++) {
                acc[r][0] = fmaf(uv[r], w.x, acc[r][0]);
                acc[r][1] = fmaf(uv[r], w.y, acc[r][1]);
                acc[r][2] = fmaf(uv[r], w.z, acc[r][2]);
                acc[r][3] = fmaf(uv[r], w.w, acc[r][3]);
            }
        }
        #pragma unroll
        for (int r = 0; r < 4; r++)
            #pragma unroll
            for (int c = 0; c < 4; c++)
                h_sm[(r0 + r) * 65 + c0 + c] += acc[r][c] + b2s[c0 + c];
    }
    __syncthreads();

    // LayerNorm per token (thread per token; padded rows -> conflict-free)
    if (tid < TOK) {
        float s = 0.f, ss = 0.f;
        #pragma unroll 8
        for (int j = 0; j < HH; j++) {
            float x = h_sm[tid * 65 + j];
            s += x; ss += x * x;
        }
        float mu = s * (1.f / HH);
        float var = ss * (1.f / HH) - mu * mu;
        float rs = rsqrtf(var + 1e-5f);
        #pragma unroll 8
        for (int j = 0; j < HH; j++) {
            float x = h_sm[tid * 65 + j];
            h_sm[tid * 65 + j] = (x - mu) * rs * gs[j] + bs[j];
        }
    }
    __syncthreads();

    // GEMM3: k = hn @ kpW -> g_kall. 4 tok x 4 col per thread.
    {
        const int r0 = tt * 4, c0 = ct * 4;
        float acc[4][4];
        #pragma unroll
        for (int r = 0; r < 4; r++)
            #pragma unroll
            for (int c = 0; c < 4; c++) acc[r][c] = 0.f;
        #pragma unroll 4
        for (int j = 0; j < HH; j++) {
            float4 w = *(const float4*)&kp_sm[j * HH + c0];
            float hv[4];
            #pragma unroll
            for (int r = 0; r < 4; r++) hv[r] = h_sm[(r0 + r) * 65 + j];
            #pragma unroll
            for (int r = 0; r < 4; r++) {
                acc[r][0] = fmaf(hv[r], w.x, acc[r][0]);
                acc[r][1] = fmaf(hv[r], w.y, acc[r][1]);
                acc[r][2] = fmaf(hv[r], w.z, acc[r][2]);
                acc[r][3] = fmaf(hv[r], w.w, acc[r][3]);
            }
        }
        #pragma unroll
        for (int r = 0; r < 4; r++)
            #pragma unroll
            for (int c = 0; c < 4; c++)
                g_kall[(tok0 + r0 + r) * HH + c0 + c] = acc[r][c];
    }
}

// ---------------------------------------------------------------------------
// Kernel 2: sequential associative-memory scan. 1 block per batch, 64 threads,
// M row per thread in registers. One __syncthreads per step (double-buffered
// ks/red, k-row cached in registers for the rank-1 update).
// Then read = M@q, r2 = read@rpW + rpb.
// ---------------------------------------------------------------------------
__global__ void __launch_bounds__(64, 1) k2_scan(const float* __restrict__ rpW,
                                                 const float* __restrict__ rpb) {
    const int b = blockIdx.x;
    const int i = threadIdx.x;
    __shared__ float ks[2][64];
    __shared__ float red[2][2][4];
    __shared__ float rds[64];

    float M[64];
    #pragma unroll
    for (int j = 0; j < 64; j++) M[j] = 0.f;

    const float* kb = g_kall + b * LL * HH;
    float kc = kb[i];
    ks[0][i] = kc;
    __syncthreads();

    for (int t = 0; t < LL - 1; t++) {
        const int p = t & 1;
        float knx = kb[(t + 1) * HH + i];   // prefetch next (final iter loads q)

        float kr[64];
        float v0 = 0.f, v1 = 0.f, v2 = 0.f, v3 = 0.f;
        #pragma unroll
        for (int j = 0; j < 64; j += 4) {
            kr[j]     = ks[p][j];
            kr[j + 1] = ks[p][j + 1];
            kr[j + 2] = ks[p][j + 2];
            kr[j + 3] = ks[p][j + 3];
            v0 = fmaf(M[j],     kr[j],     v0);
            v1 = fmaf(M[j + 1], kr[j + 1], v1);
            v2 = fmaf(M[j + 2], kr[j + 2], v2);
            v3 = fmaf(M[j + 3], kr[j + 3], v3);
        }
        float vpk = (v0 + v1) + (v2 + v3);

        // combined 3-value reduction: kk, k.vpk, vpk.vpk
        float pa = kc * kc, pb = kc * vpk, pc = vpk * vpk;
        #pragma unroll
        for (int off = 16; off; off >>= 1) {
            pa += __shfl_xor_sync(0xffffffffu, pa, off);
            pb += __shfl_xor_sync(0xffffffffu, pb, off);
            pc += __shfl_xor_sync(0xffffffffu, pc, off);
        }
        if ((i & 31) == 0) {
            int w = i >> 5;
            red[p][w][0] = pa; red[p][w][1] = pb; red[p][w][2] = pc;
        }
        ks[p ^ 1][i] = knx;    // publish next step's k before the barrier
        __syncthreads();

        float kk = red[p][0][0] + red[p][1][0];
        float kv = red[p][0][1] + red[p][1][1];
        float vv = red[p][0][2] + red[p][1][2];
        float rinv = 1.0f / fmaxf(sqrtf(kk), 1e-12f);
        // ||err||^2 = kk - 2*rinv*kv + rinv^2*vv
        float err2 = fmaf(rinv * rinv, vv, kk) - 2.0f * rinv * kv;
        if (err2 >= 0.16f * kk) {   // gate: ||err|| >= 0.4*||k||
            float s = (kc - rinv * vpk) * rinv;   // err_i * rinv
            #pragma unroll
            for (int j = 0; j < 64; j++) M[j] = fmaf(s, kr[j], M[j]);
        }
        kc = knx;
    }

    // read = M @ q   (q resides in ks[(LL-1)&1])
    const int pq = (LL - 1) & 1;
    {
        float v0 = 0.f, v1 = 0.f, v2 = 0.f, v3 = 0.f;
        #pragma unroll
        for (int j = 0; j < 64; j += 4) {
            v0 = fmaf(M[j],     ks[pq][j],     v0);
            v1 = fmaf(M[j + 1], ks[pq][j + 1], v1);
            v2 = fmaf(M[j + 2], ks[pq][j + 2], v2);
            v3 = fmaf(M[j + 3], ks[pq][j + 3], v3);
        }
        rds[i] = (v0 + v1) + (v2 + v3);
    }
    __syncthreads();

    // r2[b][i] = read . rpW[:, i] + rpb[i]
    float acc = rpb[i];
    #pragma unroll 8
    for (int j = 0; j < 64; j++) acc = fmaf(rds[j], rpW[j * HH + i], acc);
    g_r2[b * HH + i] = acc;
}

// ---------------------------------------------------------------------------
// Kernel 3: out[b][v] = r2[b] . outW[:, v] + outb[v]
// 250 blocks x 128 threads; thread owns one v for all 64 batches.
// outW read exactly once (memory-bound floor ~2us).
// ---------------------------------------------------------------------------
__global__ void k3_out(const float* __restrict__ outW,
                       const float* __restrict__ outb,
                       float* __restrict__ out) {
    __shared__ float r2s[64 * 64];
    const int tid = threadIdx.x;
    for (int idx = tid; idx < 64 * 64; idx += 128) r2s[idx] = g_r2[idx];
    __syncthreads();

    const int v = blockIdx.x * 128 + tid;
    float acc[64];
    #pragma unroll
    for (int bb = 0; bb < 64; bb++) acc[bb] = 0.f;

    #pragma unroll 4
    for (int j = 0; j < 64; j++) {
        float w = outW[j * VV + v];
        #pragma unroll
        for (int bb = 0; bb < 64; bb++)
            acc[bb] = fmaf(r2s[bb * 64 + j], w, acc[bb]);
    }
    float ob = outb[v];
    #pragma unroll
    for (int bb = 0; bb < 64; bb++) out[bb * VV + v] = acc[bb] + ob;
}

// ---------------------------------------------------------------------------
extern "C" void kernel_launch(void* const* d_in, const int* in_sizes, int n_in,
                              void* d_out, int out_size) {
    const int*   seq   = (const int*)d_in[0];
    const float* embed = (const float*)d_in[1];
    const float* W1    = (const float*)d_in[2];
    const float* b1    = (const float*)d_in[3];
    const float* W2    = (const float*)d_in[4];
    const float* b2    = (const float*)d_in[5];
    const float* gamma = (const float*)d_in[6];
    const float* beta  = (const float*)d_in[7];
    const float* kpW   = (const float*)d_in[8];
    const float* rpW   = (const float*)d_in[9];
    const float* rpb   = (const float*)d_in[10];
    const float* outW  = (const float*)d_in[11];
    const float* outb  = (const float*)d_in[12];
    float* out = (float*)d_out;

    const int smem1 = (TOK * 65 + HH * H2 + TOK * H2 + H2 * HH + HH * HH
                       + H2 + 3 * HH) * (int)sizeof(float);
    cudaFuncSetAttribute(k1_frontend, cudaFuncAttributeMaxDynamicSharedMemorySize, smem1);

    k1_frontend<<<(BB * LL) / TOK, 256, smem1>>>(seq, embed, W1, b1, W2, b2,
                                                 gamma, beta, kpW);
    k2_scan<<<BB, 64>>>(rpW, rpb);
    k3_out<<<VV / 128, 128>>>(outW, outb, out);
}

// round 2
// speedup vs baseline: 1.0616x; 1.0616x over previous
#include <cuda_runtime.h>
#include <cuda_bf16.h>
#include <math.h>

#define BB 64
#define LL 1024
#define HH 64
#define H2 128
#define VV 32000
#define TOK 128
#define HPAD 68

// Scratch (device globals; no allocation allowed)
__device__ float  g_kall[BB * LL * HH];   // 16 MB
__device__ float4 g_meta[BB * LL];        // (rinv, 0.84*kk, dot(k_t,k_{t+1}), 0)
__device__ float  g_r2[BB * HH];

// ---------------------------------------------------------------------------
// Kernel 1: per-token front-end: h=embed[seq]; u=relu(hW1+b1); x=uW2+b2+h;
//           LN(x); k = LN(x) @ kpW  -> g_kall
// 512 threads, 128 tokens per block, weights staged in smem once per block.
// ---------------------------------------------------------------------------
__global__ void __launch_bounds__(512) k1_frontend(
        const int* __restrict__ seq, const float* __restrict__ embed,
        const float* __restrict__ W1, const float* __restrict__ b1,
        const float* __restrict__ W2, const float* __restrict__ b2,
        const float* __restrict__ gamma, const float* __restrict__ beta,
        const float* __restrict__ kpW) {
    extern __shared__ float sm[];
    float* h_sm  = sm;                     // TOK * HPAD
    float* w1_sm = h_sm  + TOK * HPAD;     // 64*128
    float* u_sm  = w1_sm + HH * H2;        // 128*128
    float* w2_sm = u_sm  + TOK * H2;       // 128*64
    float* kp_sm = w2_sm + H2 * HH;        // 64*64
    float* b1s   = kp_sm + HH * HH;        // 128
    float* b2s   = b1s + H2;               // 64
    float* gsm   = b2s + HH;               // 64
    float* bsm   = gsm + HH;               // 64

    const int tid  = threadIdx.x;
    const int tok0 = blockIdx.x * TOK;

    for (int idx = tid; idx < HH * H2; idx += 512) w1_sm[idx] = W1[idx];
    for (int idx = tid; idx < H2 * HH; idx += 512) w2_sm[idx] = W2[idx];
    for (int idx = tid; idx < HH * HH; idx += 512) kp_sm[idx] = kpW[idx];
    if (tid < H2) b1s[tid] = b1[tid];
    if (tid < HH) { b2s[tid] = b2[tid]; gsm[tid] = gamma[tid]; bsm[tid] = beta[tid]; }

    // gather h (random embed rows; coalesced within each 256B row)
    #pragma unroll
    for (int k = 0; k < 16; k++) {
        int idx = tid + 512 * k;
        int t = idx >> 6, j = idx & 63;
        int row = seq[tok0 + t];
        h_sm[t * HPAD + j] = embed[row * HH + j];
    }
    __syncthreads();

    const int tt = tid >> 4;   // 0..31
    const int ct = tid & 15;   // 0..15

    // GEMM1: u[128][128] = relu(h @ W1 + b1); 4 tok x 8 col per thread
    {
        const int r0 = tt * 4, c0 = ct * 8;
        float acc[4][8];
        #pragma unroll
        for (int r = 0; r < 4; r++)
            #pragma unroll
            for (int c = 0; c < 8; c++) acc[r][c] = 0.f;
        #pragma unroll 2
        for (int j4 = 0; j4 < HH; j4 += 4) {
            float hv[4][4];
            #pragma unroll
            for (int r = 0; r < 4; r++)
                *(float4*)hv[r] = *(const float4*)&h_sm[(r0 + r) * HPAD + j4];
            #pragma unroll
            for (int jj = 0; jj < 4; jj++) {
                float4 wA = *(const float4*)&w1_sm[(j4 + jj) * H2 + c0];
                float4 wB = *(const float4*)&w1_sm[(j4 + jj) * H2 + c0 + 4];
                #pragma unroll
                for (int r = 0; r < 4; r++) {
                    float hvv = hv[r][jj];
                    acc[r][0] = fmaf(hvv, wA.x, acc[r][0]);
                    acc[r][1] = fmaf(hvv, wA.y, acc[r][1]);
                    acc[r][2] = fmaf(hvv, wA.z, acc[r][2]);
                    acc[r][3] = fmaf(hvv, wA.w, acc[r][3]);
                    acc[r][4] = fmaf(hvv, wB.x, acc[r][4]);
                    acc[r][5] = fmaf(hvv, wB.y, acc[r][5]);
                    acc[r][6] = fmaf(hvv, wB.z, acc[r][6]);
                    acc[r][7] = fmaf(hvv, wB.w, acc[r][7]);
                }
            }
        }
        #pragma unroll
        for (int r = 0; r < 4; r++)
            #pragma unroll
            for (int c = 0; c < 8; c++)
                u_sm[(r0 + r) * H2 + c0 + c] = fmaxf(acc[r][c] + b1s[c0 + c], 0.f);
    }
    __syncthreads();

    // GEMM2 + residual: x = u @ W2 + b2 + h, in-place into h_sm. 4 tok x 4 col.
    {
        const int r0 = tt * 4, c0 = ct * 4;
        float acc[4][4];
        #pragma unroll
        for (int r = 0; r < 4; r++)
            #pragma unroll
            for (int c = 0; c < 4; c++) acc[r][c] = 0.f;
        #pragma unroll 2
        for (int j4 = 0; j4 < H2; j4 += 4) {
            float uv[4][4];
            #pragma unroll
            for (int r = 0; r < 4; r++)
                *(float4*)uv[r] = *(const float4*)&u_sm[(r0 + r) * H2 + j4];
            #pragma unroll
            for (int jj = 0; jj < 4; jj++) {
                float4 w = *(const float4*)&w2_sm[(j4 + jj) * HH + c0];
                #pragma unroll
                for (int r = 0; r < 4; r++) {
                    float uvv = uv[r][jj];
                    acc[r][0] = fmaf(uvv, w.x, acc[r][0]);
                    acc[r][1] = fmaf(uvv, w.y, acc[r][1]);
                    acc[r][2] = fmaf(uvv, w.z, acc[r][2]);
                    acc[r][3] = fmaf(uvv, w.w, acc[r][3]);
                }
            }
        }
        #pragma unroll
        for (int r = 0; r < 4; r++)
            #pragma unroll
            for (int c = 0; c < 4; c++)
                h_sm[(r0 + r) * HPAD + c0 + c] += acc[r][c] + b2s[c0 + c];
    }
    __syncthreads();

    // LayerNorm per token (thread per token)
    if (tid < TOK) {
        float s = 0.f, ss = 0.f;
        #pragma unroll 8
        for (int j = 0; j < HH; j++) {
            float x = h_sm[tid * HPAD + j];
            s += x; ss += x * x;
        }
        float mu = s * (1.f / HH);
        float var = ss * (1.f / HH) - mu * mu;
        float rs = rsqrtf(var + 1e-5f);
        #pragma unroll 8
        for (int j = 0; j < HH; j++) {
            float x = h_sm[tid * HPAD + j];
            h_sm[tid * HPAD + j] = (x - mu) * rs * gsm[j] + bsm[j];
        }
    }
    __syncthreads();

    // GEMM3: k = hn @ kpW -> g_kall. 4 tok x 4 col per thread.
    {
        const int r0 = tt * 4, c0 = ct * 4;
        float acc[4][4];
        #pragma unroll
        for (int r = 0; r < 4; r++)
            #pragma unroll
            for (int c = 0; c < 4; c++) acc[r][c] = 0.f;
        #pragma unroll 2
        for (int j4 = 0; j4 < HH; j4 += 4) {
            float hv[4][4];
            #pragma unroll
            for (int r = 0; r < 4; r++)
                *(float4*)hv[r] = *(const float4*)&h_sm[(r0 + r) * HPAD + j4];
            #pragma unroll
            for (int jj = 0; jj < 4; jj++) {
                float4 w = *(const float4*)&kp_sm[(j4 + jj) * HH + c0];
                #pragma unroll
                for (int r = 0; r < 4; r++) {
                    float hvv = hv[r][jj];
                    acc[r][0] = fmaf(hvv, w.x, acc[r][0]);
                    acc[r][1] = fmaf(hvv, w.y, acc[r][1]);
                    acc[r][2] = fmaf(hvv, w.z, acc[r][2]);
                    acc[r][3] = fmaf(hvv, w.w, acc[r][3]);
                }
            }
        }
        #pragma unroll
        for (int r = 0; r < 4; r++)
            #pragma unroll
            for (int c = 0; c < 4; c++)
                g_kall[(tok0 + r0 + r) * HH + c0 + c] = acc[r][c];
    }
}

// ---------------------------------------------------------------------------
// Kernel 1b: per-(b,t) scan metadata: rinv, 0.84*kk, dot(k_t, k_{t+1}).
// One warp per (b,t), 2 elements per lane.
// ---------------------------------------------------------------------------
__global__ void k1b_meta() {
    const int g    = blockIdx.x * 8 + (threadIdx.x >> 5);
    const int lane = threadIdx.x & 31;
    const int b = g >> 10, t = g & 1023;
    if (t >= LL - 1) return;
    const float* kt = g_kall + (b * LL + t) * HH;
    float2 k0 = *(const float2*)&kt[lane * 2];
    float2 k1 = *(const float2*)&kt[HH + lane * 2];
    float pkk = k0.x * k0.x + k0.y * k0.y;
    float pdt = k0.x * k1.x + k0.y * k1.y;
    #pragma unroll
    for (int off = 16; off; off >>= 1) {
        pkk += __shfl_xor_sync(0xffffffffu, pkk, off);
        pdt += __shfl_xor_sync(0xffffffffu, pdt, off);
    }
    if (lane == 0) {
        float rinv = 1.0f / fmaxf(sqrtf(pkk), 1e-12f);
        g_meta[b * LL + t] = make_float4(rinv, 0.84f * pkk, pdt, 0.f);
    }
}

// ---------------------------------------------------------------------------
// Kernel 2: sequential scan with one-step DEFERRED rank-1 update.
// vpk_t = (M_{t-2} @ k_t) + gate_{t-1} * s_{t-1,i} * dot(k_{t-1}, k_t)
// so the reduction/gate of step t-1 is off the matvec's critical path.
// 64 threads (M row per thread), one __syncthreads per step.
// ---------------------------------------------------------------------------
__global__ void __launch_bounds__(64, 1) k2_scan(const float* __restrict__ rpW,
                                                 const float* __restrict__ rpb) {
    const int b = blockIdx.x;
    const int i = threadIdx.x;
    __shared__ float  kbuf[4][64];
    __shared__ float2 red[2][2];
    __shared__ float  rds[64];

    float M[64];
    #pragma unroll
    for (int j = 0; j < 64; j++) M[j] = 0.f;

    const float*  kb = g_kall + b * LL * HH;
    const float4* mb = g_meta + b * LL;

    float kc_cur = kb[i];            // k^0_i
    float kc_nxt = kb[HH + i];       // k^1_i
    float xA     = kb[2 * HH + i];   // k^2_i (to publish at iter 0)
    kbuf[0][i] = kc_cur;
    kbuf[1][i] = kc_nxt;
    float4 mt = mb[0];
    float a = 0.f, gs_prev = 0.f, dot_prev = 0.f;
    int gate_prev = 0;
    __syncthreads();

    for (int t = 0; t < LL - 1; t++) {
        // deep prefetch: k^{t+3} (consumed/published next iter)
        float xB = 0.f;
        if (t <= LL - 4) xB = kb[(t + 3) * HH + i];
        float4 mtn = mb[t + 1];      // meta for step t+1 (in-bounds; last unused)

        // 1. vpk_t with deferred-update correction
        float vpk = fmaf(gs_prev, dot_prev, a);

        // 2. partial reductions for kv = k.vpk, vv = vpk.vpk
        float pkv = kc_cur * vpk, pvv = vpk * vpk;
        #pragma unroll
        for (int off = 16; off; off >>= 1) {
            pkv += __shfl_xor_sync(0xffffffffu, pkv, off);
            pvv += __shfl_xor_sync(0xffffffffu, pvv, off);
        }
        const int p = t & 1;
        if ((i & 31) == 0) red[p][i >> 5] = make_float2(pkv, pvv);

        // publish k^{t+2}
        kbuf[(t + 2) & 3][i] = xA;

        // 3. apply deferred update (step t-1): M += s_{t-1} * k^{t-1}
        if (gate_prev) {
            const float* kp = kbuf[(t + 3) & 3];   // == (t-1) & 3
            #pragma unroll
            for (int j = 0; j < 64; j += 4) {
                float4 k4 = *(const float4*)&kp[j];
                M[j]     = fmaf(gs_prev, k4.x, M[j]);
                M[j + 1] = fmaf(gs_prev, k4.y, M[j + 1]);
                M[j + 2] = fmaf(gs_prev, k4.z, M[j + 2]);
                M[j + 3] = fmaf(gs_prev, k4.w, M[j + 3]);
            }
        }

        // 4. matvec for step t+1: a = M_{t-1} @ k^{t+1}
        {
            const float* kn = kbuf[(t + 1) & 3];
            float v0 = 0.f, v1 = 0.f, v2 = 0.f, v3 = 0.f;
            #pragma unroll
            for (int j = 0; j < 64; j += 4) {
                float4 k4 = *(const float4*)&kn[j];
                v0 = fmaf(M[j],     k4.x, v0);
                v1 = fmaf(M[j + 1], k4.y, v1);
                v2 = fmaf(M[j + 2], k4.z, v2);
                v3 = fmaf(M[j + 3], k4.w, v3);
            }
            a = (v0 + v1) + (v2 + v3);
        }

        // 5. combine + gate for step t
        __syncthreads();
        float2 r0 = red[p][0], r1 = red[p][1];
        float kv = r0.x + r1.x, vv = r0.y + r1.y;
        float rinv = mt.x;
        // gate  <=>  0.84*kk + rinv*(rinv*vv - 2*kv) >= 0
        int gate = fmaf(rinv, fmaf(rinv, vv, -2.f * kv), mt.y) >= 0.f;
        float s = (kc_cur - rinv * vpk) * rinv;
        gs_prev = gate ? s : 0.f;
        gate_prev = gate;
        dot_prev = mt.z;
        mt = mtn;
        kc_cur = kc_nxt; kc_nxt = xA; xA = xB;
    }

    // read = M_{L-2} @ q : a holds M_{L-3}@q, correction covers the last update
    float readv = fmaf(gs_prev, dot_prev, a);
    rds[i] = readv;
    __syncthreads();

    // r2[b][i] = read . rpW[:, i] + rpb[i]
    float acc = rpb[i];
    #pragma unroll 8
    for (int j = 0; j < 64; j++) acc = fmaf(rds[j], rpW[j * HH + i], acc);
    g_r2[b * HH + i] = acc;
}

// ---------------------------------------------------------------------------
// Kernel 3: out[b][v] = r2[b] . outW[:, v] + outb[v]
// ---------------------------------------------------------------------------
__global__ void k3_out(const float* __restrict__ outW,
                       const float* __restrict__ outb,
                       float* __restrict__ out) {
    __shared__ float r2s[64 * 64];
    const int tid = threadIdx.x;
    for (int idx = tid; idx < 64 * 64; idx += 128) r2s[idx] = g_r2[idx];
    __syncthreads();

    const int v = blockIdx.x * 128 + tid;
    float acc[64];
    #pragma unroll
    for (int bb = 0; bb < 64; bb++) acc[bb] = 0.f;

    #pragma unroll 4
    for (int j = 0; j < 64; j++) {
        float w = outW[j * VV + v];
        #pragma unroll
        for (int bb = 0; bb < 64; bb++)
            acc[bb] = fmaf(r2s[bb * 64 + j], w, acc[bb]);
    }
    float ob = outb[v];
    #pragma unroll
    for (int bb = 0; bb < 64; bb++) out[bb * VV + v] = acc[bb] + ob;
}

// ---------------------------------------------------------------------------
extern "C" void kernel_launch(void* const* d_in, const int* in_sizes, int n_in,
                              void* d_out, int out_size) {
    const int*   seq   = (const int*)d_in[0];
    const float* embed = (const float*)d_in[1];
    const float* W1    = (const float*)d_in[2];
    const float* b1    = (const float*)d_in[3];
    const float* W2    = (const float*)d_in[4];
    const float* b2    = (const float*)d_in[5];
    const float* gamma = (const float*)d_in[6];
    const float* beta  = (const float*)d_in[7];
    const float* kpW   = (const float*)d_in[8];
    const float* rpW   = (const float*)d_in[9];
    const float* rpb   = (const float*)d_in[10];
    const float* outW  = (const float*)d_in[11];
    const float* outb  = (const float*)d_in[12];
    float* out = (float*)d_out;

    const int smem1 = (TOK * HPAD + HH * H2 + TOK * H2 + H2 * HH + HH * HH
                       + H2 + 3 * HH) * (int)sizeof(float);
    cudaFuncSetAttribute(k1_frontend, cudaFuncAttributeMaxDynamicSharedMemorySize, smem1);

    k1_frontend<<<(BB * LL) / TOK, 512, smem1>>>(seq, embed, W1, b1, W2, b2,
                                                 gamma, beta, kpW);
    k1b_meta<<<(BB * LL) / 8, 256>>>();
    k2_scan<<<BB, 64>>>(rpW, rpb);
    k3_out<<<VV / 128, 128>>>(outW, outb, out);
}